// round 1
// baseline (speedup 1.0000x reference)
#include <cuda_runtime.h>
#include <math_constants.h>
#include <cstdint>

#define NB 8
#define LL 1024
#define KNB 30
#define NRBF 16
#define EF 128
#define EIN 416
#define MAXREL 32

// Output layout (floats): h_V zeros | E | E_idx(float)
#define OFF_E    (NB*LL*EF)                  // 1,048,576
#define OFF_EIDX (OFF_E + (size_t)NB*LL*KNB*EF)  // 32,505,856

__device__ float g_Cb[NB*LL*3];
__device__ int   g_Eidx[NB*LL*KNB];
__device__ float g_Dn[NB*LL*KNB];

// atom codes: 0=N,1=Ca,2=C,3=O,4=Cb ; 24 pairs (A at i, B at j)
__constant__ int c_pa[24] = {0,2,3,4,1,1,1,1,0,0,0,4,4,3,0,2,3,4,2,3,4,2,3,2};
__constant__ int c_pb[24] = {0,2,3,4,0,2,3,4,2,3,4,2,3,2,1,1,1,1,0,0,0,4,4,3};

__global__ void zero_hv_kernel(float* out) {
    int i = blockIdx.x * blockDim.x + threadIdx.x;
    if (i < NB*LL*EF) out[i] = 0.0f;
}

__global__ void cb_kernel(const float* __restrict__ X) {
    int i = blockIdx.x * blockDim.x + threadIdx.x;
    if (i >= NB*LL) return;
    const float* x = X + (size_t)i * 12;
    float bx = x[3]-x[0], by = x[4]-x[1], bz = x[5]-x[2];   // Ca - N
    float cx = x[6]-x[3], cy = x[7]-x[4], cz = x[8]-x[5];   // C - Ca
    float ax = by*cz - bz*cy;
    float ay = bz*cx - bx*cz;
    float az = bx*cy - by*cx;
    g_Cb[i*3+0] = -0.58273431f*ax + 0.56802827f*bx - 0.54067466f*cx + x[3];
    g_Cb[i*3+1] = -0.58273431f*ay + 0.56802827f*by - 0.54067466f*cy + x[4];
    g_Cb[i*3+2] = -0.58273431f*az + 0.56802827f*bz - 0.54067466f*cz + x[5];
}

// One block per (b,i) row: distances to all j, masked, D_adjust, iterative top-30 argmin.
__global__ void __launch_bounds__(256) topk_kernel(const float* __restrict__ X,
                                                   const float* __restrict__ mask,
                                                   float* __restrict__ out) {
    __shared__ float sx[LL], sy[LL], sz[LL], smk[LL], sD[LL], sA[LL];
    __shared__ float rv[256];
    __shared__ int   ri[256];
    __shared__ float sDmax;

    int row = blockIdx.x;            // b*L + i
    int bb  = row >> 10;
    int i   = row & 1023;
    int tid = threadIdx.x;

    for (int j = tid; j < LL; j += 256) {
        const float* x = X + (size_t)(bb*LL + j) * 12;
        sx[j] = x[3]; sy[j] = x[4]; sz[j] = x[5];
        smk[j] = mask[bb*LL + j];
    }
    __syncthreads();

    float cx = sx[i], cy = sy[i], cz = sz[i], mi = smk[i];
    float lmax = -CUDART_INF_F;
    for (int j = tid; j < LL; j += 256) {
        float dx = sx[j]-cx, dy = sy[j]-cy, dz = sz[j]-cz;
        float D = mi * smk[j] * sqrtf(dx*dx + dy*dy + dz*dz + 1e-6f);
        sD[j] = D;
        lmax = fmaxf(lmax, D);
    }
    rv[tid] = lmax; __syncthreads();
    for (int s = 128; s; s >>= 1) {
        if (tid < s) rv[tid] = fmaxf(rv[tid], rv[tid+s]);
        __syncthreads();
    }
    if (tid == 0) sDmax = rv[0];
    __syncthreads();
    float Dmax = sDmax;
    for (int j = tid; j < LL; j += 256)
        sA[j] = sD[j] + (1.0f - mi*smk[j]) * Dmax;
    __syncthreads();

    for (int kn = 0; kn < KNB; kn++) {
        float bv = CUDART_INF_F; int bi = LL;
        for (int j = tid; j < LL; j += 256) {
            float v = sA[j];
            if (v < bv) { bv = v; bi = j; }   // ascending scan -> lowest idx on tie
        }
        rv[tid] = bv; ri[tid] = bi;
        __syncthreads();
        for (int s = 128; s; s >>= 1) {
            if (tid < s) {
                float v2 = rv[tid+s]; int i2 = ri[tid+s];
                if (v2 < rv[tid] || (v2 == rv[tid] && i2 < ri[tid])) { rv[tid] = v2; ri[tid] = i2; }
            }
            __syncthreads();
        }
        if (tid == 0) {
            int jm = ri[0];
            g_Eidx[row*KNB + kn] = jm;
            g_Dn[row*KNB + kn]   = rv[0];          // top-k value of D_adjust
            out[OFF_EIDX + (size_t)row*KNB + kn] = (float)jm;
            sA[jm] = CUDART_INF_F;
        }
        __syncthreads();
    }
}

__device__ __forceinline__ void load_atom(const float* __restrict__ X, int code, int gr,
                                          float& x, float& y, float& z) {
    if (code == 4) {
        const float* p = g_Cb + (size_t)gr*3;
        x = p[0]; y = p[1]; z = p[2];
    } else {
        const float* p = X + (size_t)gr*12 + code*3;
        x = p[0]; y = p[1]; z = p[2];
    }
}

#define FMA2(acc, w, e) asm("fma.rn.f32x2 %0, %1, %2, %0;" : "+l"(acc) : "l"(w), "l"(e))
#define PACK2(dst, s)   asm("mov.b64 %0, {%1, %1};" : "=l"(dst) : "r"(__float_as_uint(s)))

// One block per residue PAIR (2 residues = 60 edges). 256 threads.
// Smem: edge feature pairs as f32x2: [2 residues][15 edge-pairs][416 cols] doubles = 99,840 B.
__global__ void __launch_bounds__(256, 2) edge_kernel(
    const float* __restrict__ X,
    const int*   __restrict__ ridx,
    const int*   __restrict__ chain,
    const float* __restrict__ posW,
    const float* __restrict__ posb,
    const float* __restrict__ W,
    const float* __restrict__ gamma,
    const float* __restrict__ beta,
    float* __restrict__ out)
{
    extern __shared__ float smem[];   // 24960 floats
    int tid = threadIdx.x;
    int pr  = blockIdx.x;             // residue pair id
    int rg0 = pr * 2;                 // global residue index base (b*L+i)
    int bb  = rg0 >> 10;

    // ---- Phase A: RBF features (2 * 30 * 25 = 1500 tasks) ----
    for (int t = tid; t < 1500; t += 256) {
        int r   = t / 750;
        int rem = t - r*750;
        int kn  = rem / 25;
        int p   = rem - kn*25;
        int rg  = rg0 + r;
        int j   = g_Eidx[rg*KNB + kn];
        float d;
        if (p == 0) {
            d = g_Dn[rg*KNB + kn];
        } else {
            float ax, ay, az, bx, by, bz;
            load_atom(X, c_pa[p-1], rg, ax, ay, az);
            load_atom(X, c_pb[p-1], bb*LL + j, bx, by, bz);
            float dx = ax-bx, dy = ay-by, dz = az-bz;
            d = sqrtf(dx*dx + dy*dy + dz*dz + 1e-6f);
        }
        int cbase = 16 + p*16;
        int pairi = kn >> 1, sub = kn & 1;
        float* dst = smem + (size_t)(((r*15 + pairi)*EIN) + cbase)*2 + sub;
        #pragma unroll
        for (int m = 0; m < NRBF; m++) {
            float z = (d - (2.0f + 1.3333333333f*m)) * 0.8f;
            dst[2*m] = __expf(-z*z);
        }
    }
    // ---- Phase A2: positional features (60 tasks) ----
    for (int t = tid; t < 60; t += 256) {
        int r  = t / 30;
        int kn = t - r*30;
        int rg = rg0 + r;
        int j  = g_Eidx[rg*KNB + kn];
        int gi = rg, gj = bb*LL + j;
        int dch = (chain[gi] == chain[gj]);
        int off = ridx[gi] - ridx[gj] + MAXREL;
        int dd  = dch ? min(max(off, 0), 2*MAXREL) : (2*MAXREL + 1);
        int pairi = kn >> 1, sub = kn & 1;
        float* dst = smem + (size_t)((r*15 + pairi)*EIN)*2 + sub;
        #pragma unroll
        for (int m = 0; m < 16; m++)
            dst[2*m] = posW[m*66 + dd] + posb[m];
    }
    __syncthreads();

    // ---- Phase B: matvec. thread = (f in 0..127, r in 0..1). 15 edge-pairs each. ----
    int f = tid & 127;
    int r = tid >> 7;
    const float* Wrow = W + (size_t)f * EIN;
    unsigned long long acc[15];
    #pragma unroll
    for (int p = 0; p < 15; p++) acc[p] = 0ull;

    const unsigned long long* e2 = (const unsigned long long*)smem + (size_t)r*15*EIN;
    for (int c = 0; c < EIN; c += 4) {
        float4 w4 = *(const float4*)(Wrow + c);
        unsigned long long w0, w1, w2, w3;
        PACK2(w0, w4.x); PACK2(w1, w4.y); PACK2(w2, w4.z); PACK2(w3, w4.w);
        #pragma unroll
        for (int p = 0; p < 15; p++) {
            const unsigned long long* ep = e2 + (size_t)p*EIN + c;
            ulonglong2 ea = *(const ulonglong2*)(ep);
            ulonglong2 eb = *(const ulonglong2*)(ep + 2);
            FMA2(acc[p], w0, ea.x);
            FMA2(acc[p], w1, ea.y);
            FMA2(acc[p], w2, eb.x);
            FMA2(acc[p], w3, eb.y);
        }
    }
    __syncthreads();

    // ---- write per-edge outputs to smem (reuse) : sout[60][128] ----
    float* sout = smem;
    #pragma unroll
    for (int p = 0; p < 15; p++) {
        unsigned lo = (unsigned)(acc[p] & 0xffffffffull);
        unsigned hi = (unsigned)(acc[p] >> 32);
        sout[(r*30 + 2*p    )*EF + f] = __uint_as_float(lo);
        sout[(r*30 + 2*p + 1)*EF + f] = __uint_as_float(hi);
    }
    __syncthreads();

    // ---- LayerNorm + store: 8 warps over 60 edges ----
    int wr = tid >> 5, lane = tid & 31;
    for (int e = wr; e < 60; e += 8) {
        float x0 = sout[e*EF + lane];
        float x1 = sout[e*EF + lane + 32];
        float x2 = sout[e*EF + lane + 64];
        float x3 = sout[e*EF + lane + 96];
        float s = x0 + x1 + x2 + x3;
        #pragma unroll
        for (int o = 16; o; o >>= 1) s += __shfl_xor_sync(0xffffffffu, s, o);
        float mu = s * (1.0f/128.0f);
        float d0 = x0-mu, d1 = x1-mu, d2 = x2-mu, d3 = x3-mu;
        float vs = d0*d0 + d1*d1 + d2*d2 + d3*d3;
        #pragma unroll
        for (int o = 16; o; o >>= 1) vs += __shfl_xor_sync(0xffffffffu, vs, o);
        float inv = 1.0f / sqrtf(vs * (1.0f/128.0f) + 1e-5f);
        int rr = e / 30, kn = e - rr*30;
        int rg = rg0 + rr;
        size_t base = OFF_E + ((size_t)rg*KNB + kn)*EF;
        out[base + lane     ] = d0*inv*gamma[lane     ] + beta[lane     ];
        out[base + lane + 32] = d1*inv*gamma[lane + 32] + beta[lane + 32];
        out[base + lane + 64] = d2*inv*gamma[lane + 64] + beta[lane + 64];
        out[base + lane + 96] = d3*inv*gamma[lane + 96] + beta[lane + 96];
    }
}

extern "C" void kernel_launch(void* const* d_in, const int* in_sizes, int n_in,
                              void* d_out, int out_size) {
    const float* X     = (const float*)d_in[0];
    const float* mask  = (const float*)d_in[1];
    const int*   ridx  = (const int*)  d_in[2];
    const int*   chain = (const int*)  d_in[3];
    const float* posW  = (const float*)d_in[4];
    const float* posb  = (const float*)d_in[5];
    const float* W     = (const float*)d_in[6];
    const float* gamma = (const float*)d_in[7];
    const float* beta  = (const float*)d_in[8];
    float* out = (float*)d_out;

    zero_hv_kernel<<<(NB*LL*EF + 255)/256, 256>>>(out);
    cb_kernel<<<(NB*LL + 255)/256, 256>>>(X);
    topk_kernel<<<NB*LL, 256>>>(X, mask, out);

    static bool attr_set = false;
    if (!attr_set) {
        cudaFuncSetAttribute(edge_kernel, cudaFuncAttributeMaxDynamicSharedMemorySize, 99840);
        attr_set = true;
    }
    edge_kernel<<<NB*LL/2, 256, 99840>>>(X, ridx, chain, posW, posb, W, gamma, beta, out);
}